// round 14
// baseline (speedup 1.0000x reference)
#include <cuda_runtime.h>
#include <math.h>

// Problem constants
#define BN    64
#define HW    784           // 28*28
#define CN    512
#define SA    28            // phase-1 hw splits (28-hw tiles)
#define HWPA  28
#define SB    7             // phase-2 hw splits (112-hw tiles; 448B slices)
#define HWPB  112
#define HWPB4 28            // HWPB / 4
#define NT1   (BN * SA)     // 1792 phase-1 tiles
#define NT2   (BN * SB)     // 448  phase-2 tiles
#define GRID  444           // 148 SMs * 3 CTAs (guaranteed by launch_bounds)

// Scratch (device globals: allocation-free)
__device__ float g_pval[BN * SA * CN];
__device__ int   g_pidx[BN * SA * CN];
__device__ int   g_idx [BN * CN];

// Grid-wide generation barrier (monotonic -> safe across replays AND safe
// for multiple uses per launch). Proven deadlock-free at 444 CTAs/3-per-SM
// in the R3 run.
__device__ unsigned g_bar_count = 0;
__device__ unsigned g_bar_gen   = 0;

__device__ __forceinline__ void grid_barrier() {
    __syncthreads();
    if (threadIdx.x == 0) {
        __threadfence();                                   // release
        unsigned my_gen  = atomicAdd(&g_bar_gen, 0u);
        unsigned arrived = atomicAdd(&g_bar_count, 1u);
        if (arrived == GRID - 1) {
            atomicExch(&g_bar_count, 0u);
            __threadfence();
            atomicAdd(&g_bar_gen, 1u);                     // open
        } else {
            while (atomicAdd(&g_bar_gen, 0u) == my_gen) {}
        }
        __threadfence();                                   // acquire
    }
    __syncthreads();
}

// ---------------------------------------------------------------------------
// Fused persistent kernel. Why fused: at the phase boundary ALL of x
// (103MB) + partials (7MB) fit in L2 (~126MB), so phase 2's x re-reads
// start fully L2-resident — the 3-kernel pipeline loses this to the
// inter-launch L2 decay and re-reads x from DRAM (~63us apply, measured
// 4 rounds running).
// ---------------------------------------------------------------------------
__global__ void __launch_bounds__(512, 3)
fused_kernel(const float* __restrict__ x,
             const float* __restrict__ tp,
             float* __restrict__ out) {
    const int bid = blockIdx.x;
    const int c   = threadIdx.x;

    // ---------- Phase 1: partial argmax (proven S=28 shape) ----------
    for (int t = bid; t < NT1; t += GRID) {
        const int b  = t / SA;
        const int sa = t % SA;
        const int hw0 = sa * HWPA;

        const size_t base = ((size_t)b * HW + hw0) * CN + c;

        float best = -INFINITY;
        int   bidx = hw0;

        #pragma unroll
        for (int i = 0; i < HWPA; ++i) {
            float v = x[base + (size_t)i * CN];
            if (v > best) {        // strict > + ascending i => first occurrence
                best = v;
                bidx = hw0 + i;
            }
        }

        const int o = (b * SA + sa) * CN + c;
        g_pval[o] = best;
        g_pidx[o] = bidx;
    }

    grid_barrier();

    // ---------- Combine: once per (b,c), blocks 0..63 only ----------
    // Ascending p <=> ascending hw + strict > => first occurrence.
    if (bid < BN) {
        const int b = bid;
        const size_t o0 = (size_t)b * SA * CN + c;
        float best = -INFINITY;
        int   idx  = 0;
        #pragma unroll
        for (int p = 0; p < SA; ++p) {
            float v = g_pval[o0 + (size_t)p * CN];
            if (v > best) { best = v; idx = g_pidx[o0 + (size_t)p * CN]; }
        }
        g_idx[b * CN + c] = idx;
    }

    grid_barrier();

    // ---------- Phase 2: apply (proven S=7 / 448B-slice shape) ----------
    for (int t = bid; t < NT2; t += GRID) {
        const int b = t / SB;
        const int s = t % SB;

        const int idx = g_idx[b * CN + c];     // L2-hot 131KB table

        const float4* __restrict__ trow4 =
            (const float4*)(tp + ((size_t)b * HW + (size_t)idx) * HW + s * HWPB);

        const size_t base = ((size_t)b * HW + (size_t)s * HWPB) * CN + c;

        #pragma unroll 4
        for (int j = 0; j < HWPB4; ++j) {
            const float4 t4 = __ldg(trow4 + j);
            const size_t o  = base + (size_t)(4 * j) * CN;

            float x0 = x[o];                   // L2 hits while x survives
            float x1 = x[o + (size_t)CN];
            float x2 = x[o + (size_t)(2 * CN)];
            float x3 = x[o + (size_t)(3 * CN)];

            // evict-first stores: the write-once out stream must not evict x
            __stcs(out + o,                    fmaxf(x0 * t4.x, 0.0f));
            __stcs(out + o + (size_t)CN,       fmaxf(x1 * t4.y, 0.0f));
            __stcs(out + o + (size_t)(2 * CN), fmaxf(x2 * t4.z, 0.0f));
            __stcs(out + o + (size_t)(3 * CN), fmaxf(x3 * t4.w, 0.0f));
        }
    }
}

// ---------------------------------------------------------------------------
// Launch: inputs [x, t_p]; output fp32 [64,28,28,512]. One graph node.
// ---------------------------------------------------------------------------
extern "C" void kernel_launch(void* const* d_in, const int* in_sizes, int n_in,
                              void* d_out, int out_size) {
    (void)in_sizes; (void)n_in; (void)out_size;
    const float* x   = (const float*)d_in[0];
    const float* tp  = (const float*)d_in[1];
    float*       out = (float*)d_out;

    fused_kernel<<<GRID, CN>>>(x, tp, out);
}

// round 15
// speedup vs baseline: 1.0766x; 1.0766x over previous
#include <cuda_runtime.h>
#include <math.h>

// Problem constants
#define BN    64
#define HW    784           // 28*28
#define CN    512
#define SA    28            // argmax hw splits (HWPA = 28)
#define HWPA  28
#define SB    14            // apply hw splits  (HWPB = 56; 224B ≡ 0 mod 16)
#define HWPB  56
#define HWPB4 14            // HWPB / 4

// Scratch (device globals: allocation-free)
__device__ float g_pval[BN * SA * CN];
__device__ int   g_pidx[BN * SA * CN];
__device__ int   g_idx [BN * CN];

// ---------------------------------------------------------------------------
// Kernel 1: partial argmax (proven 8x: ~19.5us, DRAM ~67%). Unchanged.
// ---------------------------------------------------------------------------
__global__ void __launch_bounds__(CN)
argmax_partial_kernel(const float* __restrict__ x) {
    const int s = blockIdx.x;
    const int b = blockIdx.y;
    const int c = threadIdx.x;
    const int hw0 = s * HWPA;

    const size_t base = ((size_t)b * HW + hw0) * CN + c;

    float best = -INFINITY;
    int   bidx = hw0;

    #pragma unroll
    for (int i = 0; i < HWPA; ++i) {
        float v = x[base + (size_t)i * CN];
        if (v > best) {            // strict > + ascending i => first occurrence
            best = v;
            bidx = hw0 + i;
        }
    }

    const int o = (b * SA + s) * CN + c;
    g_pval[o] = best;
    g_pidx[o] = bidx;
}

// ---------------------------------------------------------------------------
// Kernel 2: combine 28 partials once per (b,c) -> g_idx (131 KB, ~2.5us).
// Ascending p <=> ascending hw + strict > => first occurrence (jnp.argmax).
// ---------------------------------------------------------------------------
__global__ void __launch_bounds__(256)
combine_kernel() {
    const int tid = blockIdx.x * 256 + threadIdx.x;   // 0 .. 32767
    const int b = tid >> 9;
    const int c = tid & 511;

    const size_t o0 = (size_t)b * SA * CN + c;
    float best = -INFINITY;
    int   idx  = 0;
    #pragma unroll
    for (int p = 0; p < SA; ++p) {
        float v = g_pval[o0 + (size_t)p * CN];
        if (v > best) { best = v; idx = g_pidx[o0 + (size_t)p * CN]; }
    }
    g_idx[tid] = idx;
}

// ---------------------------------------------------------------------------
// Kernel 3: apply — the never-tested cross product of the two measured wins:
//   * 896 blocks (SB=14): fills all 592 CTA slots (148 SMs x 4 CTA) for the
//     first ~1.5 waves — R6 measured occ 62->76% from this alone.
//   * g_idx single-read prologue: removes R6's 28-deep combine (~102MB of
//     L2 reads / ~8us) that masked the occupancy gain.
// Loop body is the proven R2 shape (unroll 4, __ldg templates, plain x/out).
// Grid is (SB, BN): a batch's s-blocks are launch-adjacent so template
// slice-boundary lines (224B slices straddling 128B lines) stay L2-shared.
// ---------------------------------------------------------------------------
__global__ void __launch_bounds__(CN)
apply_kernel(const float* __restrict__ x,
             const float* __restrict__ tp,
             float* __restrict__ out) {
    const int s = blockIdx.x;
    const int b = blockIdx.y;
    const int c = threadIdx.x;

    const int idx = g_idx[b * CN + c];    // 131 KB table, L2-hot, coalesced

    // Selected template row slice: t_p[b, idx, s*56 .. s*56+55]
    // Row pitch 3136B and slice offset 224B are 16B multiples -> float4-safe.
    const float4* __restrict__ trow4 =
        (const float4*)(tp + ((size_t)b * HW + (size_t)idx) * HW + s * HWPB);

    const size_t base = ((size_t)b * HW + (size_t)s * HWPB) * CN + c;

    #pragma unroll 4
    for (int j = 0; j < HWPB4; ++j) {
        const float4 t4 = __ldg(trow4 + j);
        const size_t o  = base + (size_t)(4 * j) * CN;

        float x0 = x[o];
        float x1 = x[o + (size_t)CN];
        float x2 = x[o + (size_t)(2 * CN)];
        float x3 = x[o + (size_t)(3 * CN)];

        out[o]                    = fmaxf(x0 * t4.x, 0.0f);
        out[o + (size_t)CN]       = fmaxf(x1 * t4.y, 0.0f);
        out[o + (size_t)(2 * CN)] = fmaxf(x2 * t4.z, 0.0f);
        out[o + (size_t)(3 * CN)] = fmaxf(x3 * t4.w, 0.0f);
    }
}

// ---------------------------------------------------------------------------
// Launch: inputs [x, t_p]; output fp32 [64,28,28,512]. Graph-capturable.
// ---------------------------------------------------------------------------
extern "C" void kernel_launch(void* const* d_in, const int* in_sizes, int n_in,
                              void* d_out, int out_size) {
    (void)in_sizes; (void)n_in; (void)out_size;
    const float* x   = (const float*)d_in[0];
    const float* tp  = (const float*)d_in[1];
    float*       out = (float*)d_out;

    dim3 gridA(SA, BN);
    argmax_partial_kernel<<<gridA, CN>>>(x);

    combine_kernel<<<128, 256>>>();

    dim3 gridB(SB, BN);
    apply_kernel<<<gridB, CN>>>(x, tp, out);
}